// round 1
// baseline (speedup 1.0000x reference)
#include <cuda_runtime.h>
#include <cuda_bf16.h>
#include <math.h>

#define NTOK 4096
#define DDIM 1024
#define NEXP 8
#define CAP  1280
#define NASSIGN (2 * NTOK)          // 8192 (k-major: p = k*NTOK + n)
#define NSLOT (NEXP * CAP)          // 10240

// Output layout (fp32, concatenated in reference return order)
#define W_OFF 0ULL
#define M_OFF 41943040ULL
#define B_OFF 83886080ULL
#define L_OFF 94371840ULL
#define WM_FLOATS 83886080ULL       // W + M regions to zero-fill

// Scratch (device globals; no allocations allowed)
__device__ float g_logits[NTOK * NEXP];
__device__ int   g_topi[NTOK * 2];
__device__ float g_topp[NTOK * 2];
__device__ int   g_rank[NASSIGN];
__device__ int   g_slot[NSLOT];

// ---------------------------------------------------------------------------
// 1) Router logits: one block loops over tokens; w_gate staged in smem.
// ---------------------------------------------------------------------------
__global__ void logits_kernel(const float* __restrict__ x,
                              const float* __restrict__ w,
                              float* __restrict__ out)
{
    __shared__ float sw[NEXP * DDIM];          // 32 KB
    __shared__ float sred[8][NEXP];            // 8 warps x 8 experts

    for (int i = threadIdx.x; i < NEXP * DDIM; i += blockDim.x)
        sw[i] = w[i];
    __syncthreads();

    const int t = threadIdx.x;
    const int warp = t >> 5;
    const int lane = t & 31;

    for (int n = blockIdx.x; n < NTOK; n += gridDim.x) {
        const float* xr = x + (size_t)n * DDIM;
        float acc[NEXP];
        #pragma unroll
        for (int e = 0; e < NEXP; e++) acc[e] = 0.f;

        for (int d = t; d < DDIM; d += blockDim.x) {
            float xv = xr[d];
            #pragma unroll
            for (int e = 0; e < NEXP; e++)
                acc[e] = fmaf(xv, sw[e * DDIM + d], acc[e]);
        }
        // warp reduce each accumulator
        #pragma unroll
        for (int off = 16; off > 0; off >>= 1) {
            #pragma unroll
            for (int e = 0; e < NEXP; e++)
                acc[e] += __shfl_xor_sync(0xffffffffu, acc[e], off);
        }
        if (lane == 0) {
            #pragma unroll
            for (int e = 0; e < NEXP; e++) sred[warp][e] = acc[e];
        }
        __syncthreads();
        if (t < NEXP) {
            float v = 0.f;
            #pragma unroll
            for (int wgi = 0; wgi < 8; wgi++) v += sred[wgi][t];
            g_logits[n * NEXP + t] = v;
            out[L_OFF + (size_t)n * NEXP + t] = v;
        }
        __syncthreads();
    }
}

// ---------------------------------------------------------------------------
// 2) Top-2 + softmax over the two kept logits (jax top_k tie-break: lowest
//    index first via strict-> comparisons).
// ---------------------------------------------------------------------------
__global__ void top2_kernel()
{
    int n = blockIdx.x * blockDim.x + threadIdx.x;
    if (n >= NTOK) return;
    float v[NEXP];
    #pragma unroll
    for (int e = 0; e < NEXP; e++) v[e] = g_logits[n * NEXP + e];

    int i0 = 0; float b0 = v[0];
    #pragma unroll
    for (int e = 1; e < NEXP; e++)
        if (v[e] > b0) { b0 = v[e]; i0 = e; }
    int i1 = -1; float b1 = -INFINITY;
    #pragma unroll
    for (int e = 0; e < NEXP; e++)
        if (e != i0 && v[e] > b1) { b1 = v[e]; i1 = e; }

    // two-value softmax (b0 >= b1)
    float e0 = 1.0f;
    float e1 = __expf(b1 - b0);
    float inv = 1.0f / (e0 + e1);

    g_topi[n * 2 + 0] = i0;
    g_topi[n * 2 + 1] = i1;
    g_topp[n * 2 + 0] = e0 * inv;
    g_topp[n * 2 + 1] = e1 * inv;
}

// ---------------------------------------------------------------------------
// 3) Deterministic k-major rank: one block per expert, exclusive prefix scan
//    over the 8192 assignment positions. Each position p belongs to exactly
//    one expert, so g_rank[p] is written exactly once across the 8 blocks.
// ---------------------------------------------------------------------------
__global__ void rank_kernel()
{
    const int e = blockIdx.x;           // expert
    const int t = threadIdx.x;          // 1024 threads
    const int PER = NASSIGN / 1024;     // 8 positions per thread

    int flag[PER];
    int local[PER];
    int cnt = 0;
    #pragma unroll
    for (int i = 0; i < PER; i++) {
        int p = t * PER + i;
        int k = p >> 12;                // p / NTOK
        int n = p & (NTOK - 1);         // p % NTOK
        int ex = g_topi[n * 2 + k];
        flag[i] = (ex == e);
        local[i] = cnt;
        cnt += flag[i];
    }

    __shared__ int s[1024];
    s[t] = cnt;
    __syncthreads();
    #pragma unroll
    for (int off = 1; off < 1024; off <<= 1) {
        int vv = (t >= off) ? s[t - off] : 0;
        __syncthreads();
        s[t] += vv;
        __syncthreads();
    }
    int excl = s[t] - cnt;

    #pragma unroll
    for (int i = 0; i < PER; i++) {
        if (flag[i]) {
            int p = t * PER + i;
            g_rank[p] = excl + local[i];
        }
    }
}

// ---------------------------------------------------------------------------
// 4) Zero-fill weights+mask regions (float4 stores) and init slot map.
// ---------------------------------------------------------------------------
__global__ void fill_kernel(float* __restrict__ out)
{
    size_t i = (size_t)blockIdx.x * blockDim.x + threadIdx.x;
    const size_t nchunk = WM_FLOATS / 4;     // 20,971,520 float4s
    float4 z = make_float4(0.f, 0.f, 0.f, 0.f);
    float4* o = reinterpret_cast<float4*>(out);
    for (size_t c = i; c < nchunk; c += (size_t)gridDim.x * blockDim.x)
        o[c] = z;
    if (i < NSLOT) g_slot[i] = -1;
}

// ---------------------------------------------------------------------------
// 5) Scatter the <=8192 nonzero (weight, mask) entries + slot->token map.
// ---------------------------------------------------------------------------
__global__ void scatter_kernel(float* __restrict__ out)
{
    int p = blockIdx.x * blockDim.x + threadIdx.x;
    if (p >= NASSIGN) return;
    int k = p >> 12;
    int n = p & (NTOK - 1);
    int e = g_topi[n * 2 + k];
    int r = g_rank[p];
    if (r < CAP) {
        float pr = g_topp[n * 2 + k];
        size_t idx = (size_t)n * (NEXP * CAP) + (size_t)e * CAP + r;
        out[W_OFF + idx] = pr;
        out[M_OFF + idx] = 1.0f;
        g_slot[e * CAP + r] = n;
    }
}

// ---------------------------------------------------------------------------
// 6) expert_batches: each slot (e,c) is either a verbatim x-row copy or zeros.
// ---------------------------------------------------------------------------
__global__ void gather_kernel(const float* __restrict__ x,
                              float* __restrict__ out)
{
    int slot = blockIdx.x;              // 0..NSLOT-1
    int n = g_slot[slot];
    float4* dst = reinterpret_cast<float4*>(out + B_OFF + (size_t)slot * DDIM);
    if (n >= 0) {
        const float4* src = reinterpret_cast<const float4*>(x + (size_t)n * DDIM);
        dst[threadIdx.x] = src[threadIdx.x];
    } else {
        dst[threadIdx.x] = make_float4(0.f, 0.f, 0.f, 0.f);
    }
}

extern "C" void kernel_launch(void* const* d_in, const int* in_sizes, int n_in,
                              void* d_out, int out_size)
{
    const float* x = (const float*)d_in[0];       // [2,2048,1024]
    const float* w = (const float*)d_in[1];       // [8,1024]
    float* out = (float*)d_out;

    logits_kernel<<<512, 256>>>(x, w, out);
    top2_kernel<<<(NTOK + 255) / 256, 256>>>();
    rank_kernel<<<NEXP, 1024>>>();
    fill_kernel<<<20480, 256>>>(out);
    scatter_kernel<<<(NASSIGN + 255) / 256, 256>>>(out);
    gather_kernel<<<NSLOT, 256>>>(x, out);
}

// round 2
// speedup vs baseline: 1.0497x; 1.0497x over previous
#include <cuda_runtime.h>
#include <cuda_bf16.h>
#include <math.h>

#define NTOK 4096
#define DDIM 1024
#define NEXP 8
#define CAP  1280
#define NASSIGN (2 * NTOK)          // 8192 (k-major: p = k*NTOK + n)
#define NSLOT (NEXP * CAP)          // 10240

// Output layout (fp32, concatenated in reference return order)
#define W_OFF 0ULL
#define M_OFF 41943040ULL
#define B_OFF 83886080ULL
#define L_OFF 94371840ULL
#define WM_FLOATS 83886080ULL       // W + M regions to zero-fill

// Scratch (device globals; no allocations allowed)
__device__ int   g_topi[NTOK * 2];
__device__ float g_topp[NTOK * 2];
__device__ int   g_rank[NASSIGN];
__device__ int   g_slot[NSLOT];

// Side streams/events for graph fork-join (created pre-main; no device mem alloc)
static cudaStream_t g_s1;
static cudaEvent_t  g_evFork, g_evJoin;
namespace {
struct StreamInit {
    StreamInit() {
        cudaStreamCreateWithFlags(&g_s1, cudaStreamNonBlocking);
        cudaEventCreateWithFlags(&g_evFork, cudaEventDisableTiming);
        cudaEventCreateWithFlags(&g_evJoin, cudaEventDisableTiming);
    }
} g_streamInit;
}

// ---------------------------------------------------------------------------
// 1) Fused router logits + top-2 + softmax. One warp per token; w_gate in
//    smem. After the xor butterfly every lane holds all 8 sums, so lane 0
//    computes top-2 directly from registers (no extra kernel, no round trip).
// ---------------------------------------------------------------------------
__global__ void logits_top2_kernel(const float* __restrict__ x,
                                   const float* __restrict__ w,
                                   float* __restrict__ out)
{
    __shared__ float sw[NEXP * DDIM];          // 32 KB
    for (int i = threadIdx.x; i < NEXP * DDIM; i += blockDim.x)
        sw[i] = w[i];
    __syncthreads();

    const int warp = threadIdx.x >> 5;
    const int lane = threadIdx.x & 31;
    const int n = blockIdx.x * (blockDim.x >> 5) + warp;   // token
    if (n >= NTOK) return;

    const float* xr = x + (size_t)n * DDIM;
    float acc[NEXP];
    #pragma unroll
    for (int e = 0; e < NEXP; e++) acc[e] = 0.f;

    #pragma unroll 4
    for (int d = lane; d < DDIM; d += 32) {
        float xv = xr[d];
        #pragma unroll
        for (int e = 0; e < NEXP; e++)
            acc[e] = fmaf(xv, sw[e * DDIM + d], acc[e]);
    }
    #pragma unroll
    for (int off = 16; off > 0; off >>= 1) {
        #pragma unroll
        for (int e = 0; e < NEXP; e++)
            acc[e] += __shfl_xor_sync(0xffffffffu, acc[e], off);
    }
    // all lanes now hold the full 8 logits
    if (lane < NEXP)
        out[L_OFF + (size_t)n * NEXP + lane] = acc[lane];

    if (lane == 0) {
        int i0 = 0; float b0 = acc[0];
        #pragma unroll
        for (int e = 1; e < NEXP; e++)
            if (acc[e] > b0) { b0 = acc[e]; i0 = e; }
        int i1 = -1; float b1 = -INFINITY;
        #pragma unroll
        for (int e = 0; e < NEXP; e++)
            if (e != i0 && acc[e] > b1) { b1 = acc[e]; i1 = e; }
        float e1 = __expf(b1 - b0);
        float inv = 1.0f / (1.0f + e1);
        g_topi[n * 2 + 0] = i0;
        g_topi[n * 2 + 1] = i1;
        g_topp[n * 2 + 0] = inv;
        g_topp[n * 2 + 1] = e1 * inv;
    }
}

// ---------------------------------------------------------------------------
// 2) Deterministic k-major rank: one block per expert, exclusive prefix scan
//    over the 8192 assignment positions. Also initializes g_slot to -1
//    (8 blocks x 1024 threads cover the 10240 slots), removing the gather
//    path's dependency on the big fill kernel.
// ---------------------------------------------------------------------------
__global__ void rank_kernel()
{
    const int e = blockIdx.x;           // expert
    const int t = threadIdx.x;          // 1024 threads
    const int PER = NASSIGN / 1024;     // 8 positions per thread

    // slot map init (grid-wide, each entry written once)
    int gid = blockIdx.x * 1024 + t;    // 0..8191
    if (gid < NSLOT) g_slot[gid] = -1;
    int gid2 = gid + 8192;
    if (gid2 < NSLOT) g_slot[gid2] = -1;

    int flag[8];
    int local[8];
    int cnt = 0;
    #pragma unroll
    for (int i = 0; i < PER; i++) {
        int p = t * PER + i;
        int k = p >> 12;                // p / NTOK
        int n = p & (NTOK - 1);         // p % NTOK
        int ex = g_topi[n * 2 + k];
        flag[i] = (ex == e);
        local[i] = cnt;
        cnt += flag[i];
    }

    __shared__ int s[1024];
    s[t] = cnt;
    __syncthreads();
    #pragma unroll
    for (int off = 1; off < 1024; off <<= 1) {
        int vv = (t >= off) ? s[t - off] : 0;
        __syncthreads();
        s[t] += vv;
        __syncthreads();
    }
    int excl = s[t] - cnt;

    #pragma unroll
    for (int i = 0; i < PER; i++) {
        if (flag[i]) {
            int p = t * PER + i;
            g_rank[p] = excl + local[i];
        }
    }
}

// ---------------------------------------------------------------------------
// 3) Slot scatter (g_slot only — no dependency on the big fill).
// ---------------------------------------------------------------------------
__global__ void scatter_slot_kernel()
{
    int p = blockIdx.x * blockDim.x + threadIdx.x;
    if (p >= NASSIGN) return;
    int k = p >> 12;
    int n = p & (NTOK - 1);
    int e = g_topi[n * 2 + k];
    int r = g_rank[p];
    if (r < CAP) g_slot[e * CAP + r] = n;
}

// ---------------------------------------------------------------------------
// 4) expert_batches: each slot (e,c) is a verbatim x-row copy or zeros.
//    x was just streamed by the logits kernel -> mostly L2 hits.
// ---------------------------------------------------------------------------
__global__ void gather_kernel(const float* __restrict__ x,
                              float* __restrict__ out)
{
    int slot = blockIdx.x;              // 0..NSLOT-1
    int n = g_slot[slot];
    float4* dst = reinterpret_cast<float4*>(out + B_OFF + (size_t)slot * DDIM);
    if (n >= 0) {
        const float4* src = reinterpret_cast<const float4*>(x + (size_t)n * DDIM);
        dst[threadIdx.x] = src[threadIdx.x];
    } else {
        dst[threadIdx.x] = make_float4(0.f, 0.f, 0.f, 0.f);
    }
}

// ---------------------------------------------------------------------------
// 5) Zero-fill weights+mask regions (float4 stores) — runs on the forked
//    stream, fully overlapped with the routing/gather chain.
// ---------------------------------------------------------------------------
__global__ void fill_kernel(float* __restrict__ out)
{
    size_t i = (size_t)blockIdx.x * blockDim.x + threadIdx.x;
    const size_t nchunk = WM_FLOATS / 4;     // 20,971,520 float4s
    float4 z = make_float4(0.f, 0.f, 0.f, 0.f);
    float4* o = reinterpret_cast<float4*>(out);
    for (size_t c = i; c < nchunk; c += (size_t)gridDim.x * blockDim.x)
        o[c] = z;
}

// ---------------------------------------------------------------------------
// 6) Final sparse W/M scatter (after fill joins).
// ---------------------------------------------------------------------------
__global__ void scatter_wm_kernel(float* __restrict__ out)
{
    int p = blockIdx.x * blockDim.x + threadIdx.x;
    if (p >= NASSIGN) return;
    int k = p >> 12;
    int n = p & (NTOK - 1);
    int e = g_topi[n * 2 + k];
    int r = g_rank[p];
    if (r < CAP) {
        float pr = g_topp[n * 2 + k];
        size_t idx = (size_t)n * (NEXP * CAP) + (size_t)e * CAP + r;
        out[W_OFF + idx] = pr;
        out[M_OFF + idx] = 1.0f;
    }
}

extern "C" void kernel_launch(void* const* d_in, const int* in_sizes, int n_in,
                              void* d_out, int out_size)
{
    const float* x = (const float*)d_in[0];       // [2,2048,1024]
    const float* w = (const float*)d_in[1];       // [8,1024]
    float* out = (float*)d_out;

    // Fork: big zero-fill on side stream, routing chain on main stream.
    cudaEventRecord(g_evFork, 0);
    cudaStreamWaitEvent(g_s1, g_evFork, 0);
    fill_kernel<<<20480, 256, 0, g_s1>>>(out);

    logits_top2_kernel<<<512, 256>>>(x, w, out);
    rank_kernel<<<NEXP, 1024>>>();
    scatter_slot_kernel<<<(NASSIGN + 255) / 256, 256>>>();
    gather_kernel<<<NSLOT, 256>>>(x, out);

    // Join: W/M sparse writes need the zero-fill complete.
    cudaEventRecord(g_evJoin, g_s1);
    cudaStreamWaitEvent(0, g_evJoin, 0);
    scatter_wm_kernel<<<(NASSIGN + 255) / 256, 256>>>(out);
}